// round 8
// baseline (speedup 1.0000x reference)
#include <cuda_runtime.h>
#include <cuda_bf16.h>
#include <math.h>
#include <stdint.h>

// ---------------------------------------------------------------------------
// 25-pt (radius-4, 3-axis) wave stencil, 10 scan steps (first trivial),
// then loss = mean((out-ref)^2), max_abs = max|out-ref|.
// R8: full software pipeline — cp.async ring (distance 2) for plane tiles,
// and ALL pointwise streams (prev/vp/src) + z-queue head prefetched one
// body ahead, so no LDG is consumed in its issuing body.
// ---------------------------------------------------------------------------

#define NN 192
#define PLANE (NN * NN)
#define VOL (NN * NN * NN)

#define TXT 16
#define TY 8
#define NTHR (TXT * TY)          // 128
#define SPANX (TXT * 4)          // 64 x-points per block
#define ZC 16
#define R  4

#define TILE_H (TY + 2 * R)      // 16
#define TILE_WU (SPANX + 2 * R)  // 72 floats used
#define TILE_W 80                // padded row stride
#define FW4 (TILE_WU / 4)        // 18 float4 per row
#define NSLOT (TILE_H * FW4)     // 288 fill slots

#define C0 ((float)(-205.0 / 72.0 / 400.0))
#define C1 ((float)(8.0 / 5.0 / 400.0))
#define C2 ((float)(-1.0 / 5.0 / 400.0))
#define C3 ((float)(8.0 / 315.0 / 400.0))
#define C4 ((float)(-1.0 / 560.0 / 400.0))

__device__ float g_bufA[VOL];
__device__ float g_bufB[VOL];
__device__ double g_sum;
__device__ unsigned int g_maxbits;

__global__ void init_accum_kernel() {
    g_sum = 0.0;
    g_maxbits = 0u;
}

__device__ __forceinline__ float4 ldg4(const float* p) {
    return *reinterpret_cast<const float4*>(p);
}
__device__ __forceinline__ float4 ldcs4(const float* p) {
    float4 v;
    asm volatile("ld.global.cs.v4.f32 {%0,%1,%2,%3}, [%4];"
                 : "=f"(v.x), "=f"(v.y), "=f"(v.z), "=f"(v.w) : "l"(p));
    return v;
}
__device__ __forceinline__ float ldcs1(const float* p) {
    float v;
    asm volatile("ld.global.cs.f32 %0, [%1];" : "=f"(v) : "l"(p));
    return v;
}

__device__ __forceinline__ void fill_plane_async(
    uint32_t sbase, const float* gplane, const int* goff, const int* sidx) {
#pragma unroll
    for (int k = 0; k < 3; k++) {
        if (sidx[k] >= 0) {
            const float* srcp = (goff[k] >= 0) ? (gplane + goff[k]) : gplane;
            int sz = (goff[k] >= 0) ? 16 : 0;
            asm volatile("cp.async.cg.shared.global [%0], [%1], 16, %2;"
                         :: "r"(sbase + (uint32_t)sidx[k] * 4u), "l"(srcp), "r"(sz));
        }
    }
    asm volatile("cp.async.commit_group;" ::: "memory");
}

template <bool FINAL>
struct StepCtx {
    const float* cur;
    const float* prev;
    const float* vp;
    const float* src;
    float* out;
    const float* ref;
};

// Body for plane z. Consumes: tile(z) in ring, q[0..8]=cur(z-4..z+4),
// pv/vv/sv for plane z (prefetched last body). Issues: tile fill z+2,
// q-head z+5, pv/vv/sv for z+1 (into pn/vn/sn).
template <bool FINAL>
__device__ __forceinline__ void plane_body(
    const StepCtx<FINAL>& c,
    const float (&consume)[TILE_H][TILE_W],
    uint32_t fillbase,
    int z, bool hasprev,
    const int* goff, const int* sidx,
    int col,
    float4 q[9],
    float4& pv, float4& vv, float4& sv,   // this body's values; replaced by next
    int sx, int syc,
    double& acc_s, float& acc_m) {

    const int idx = z * PLANE + col;

    // ---- issue async tile fill for plane z+2 (clamped) ----
    {
        int zf = z + 2;
        if (zf > NN - 1) zf = NN - 1;
        fill_plane_async(fillbase, c.cur + zf * PLANE, goff, sidx);
    }

    // ---- issue next-body loads (consumed NEXT body) ----
    float4 qn;
    {
        int zp = z + 5;
        qn = (zp < NN) ? ldg4(&c.cur[zp * PLANE + col])
                       : make_float4(0.f, 0.f, 0.f, 0.f);
    }
    int zn = z + 1;
    if (zn > NN - 1) zn = NN - 1;            // stay in-range; value unused then
    const int idxn = zn * PLANE + col;
    float4 pn = hasprev ? ldg4(&c.prev[idxn]) : make_float4(0.f, 0.f, 0.f, 0.f);
    float4 vn = ldg4(&c.vp[idxn]);
    float4 sn = ldcs4(&c.src[idxn]);

    // ---- wait for tile(z), then compute ----
    asm volatile("cp.async.wait_group 2;" ::: "memory");
    __syncthreads();

    float xs[12];
#pragma unroll
    for (int j = 0; j < 3; j++) {
        float4 t = *reinterpret_cast<const float4*>(&consume[syc][sx - 4 + 4 * j]);
        xs[4 * j + 0] = t.x;
        xs[4 * j + 1] = t.y;
        xs[4 * j + 2] = t.z;
        xs[4 * j + 3] = t.w;
    }

    float lap[4];
    {
        const float* q4 = &q[4].x;
#pragma unroll
        for (int p = 0; p < 4; p++) lap[p] = (3.0f * C0) * q4[p];
    }
    {
        float4 ym = *reinterpret_cast<const float4*>(&consume[syc - 1][sx]);
        float4 yp = *reinterpret_cast<const float4*>(&consume[syc + 1][sx]);
        const float* q3 = &q[3].x;
        const float* q5 = &q[5].x;
        const float* a = &ym.x;
        const float* b = &yp.x;
#pragma unroll
        for (int p = 0; p < 4; p++)
            lap[p] += C1 * (q3[p] + q5[p] + a[p] + b[p] + xs[p + 3] + xs[p + 5]);
    }
    {
        float4 ym = *reinterpret_cast<const float4*>(&consume[syc - 2][sx]);
        float4 yp = *reinterpret_cast<const float4*>(&consume[syc + 2][sx]);
        const float* q2 = &q[2].x;
        const float* q6 = &q[6].x;
        const float* a = &ym.x;
        const float* b = &yp.x;
#pragma unroll
        for (int p = 0; p < 4; p++)
            lap[p] += C2 * (q2[p] + q6[p] + a[p] + b[p] + xs[p + 2] + xs[p + 6]);
    }
    {
        float4 ym = *reinterpret_cast<const float4*>(&consume[syc - 3][sx]);
        float4 yp = *reinterpret_cast<const float4*>(&consume[syc + 3][sx]);
        const float* q1 = &q[1].x;
        const float* q7 = &q[7].x;
        const float* a = &ym.x;
        const float* b = &yp.x;
#pragma unroll
        for (int p = 0; p < 4; p++)
            lap[p] += C3 * (q1[p] + q7[p] + a[p] + b[p] + xs[p + 1] + xs[p + 7]);
    }
    {
        float4 ym = *reinterpret_cast<const float4*>(&consume[syc - 4][sx]);
        float4 yp = *reinterpret_cast<const float4*>(&consume[syc + 4][sx]);
        const float* q0 = &q[0].x;
        const float* q8 = &q[8].x;
        const float* a = &ym.x;
        const float* b = &yp.x;
#pragma unroll
        for (int p = 0; p < 4; p++)
            lap[p] += C4 * (q0[p] + q8[p] + a[p] + b[p] + xs[p] + xs[p + 8]);
    }

    float4 upd;
    {
        const float* q4 = &q[4].x;
        const float* pvp = &pv.x;
        const float* vvp = &vv.x;
        const float* svp = &sv.x;
        float* u = &upd.x;
#pragma unroll
        for (int p = 0; p < 4; p++)
            u[p] = 2.0f * q4[p] - pvp[p] + vvp[p] * lap[p] + svp[p];
    }

    if (FINAL) {
        const float* u = &upd.x;
#pragma unroll
        for (int p = 0; p < 4; p++) {
            c.out[idx + p] = u[p];
            float e = u[p] - ldcs1(&c.ref[idx + p]);
            acc_s += (double)e * (double)e;
            acc_m = fmaxf(acc_m, fabsf(e));
        }
    } else {
        *reinterpret_cast<float4*>(&c.out[idx]) = upd;
    }

    // shift queue; commit prefetched values
#pragma unroll
    for (int k = 0; k < 8; k++) q[k] = q[k + 1];
    q[8] = qn;
    pv = pn;
    vv = vn;
    sv = sn;
}

template <bool FINAL>
__global__ void __launch_bounds__(NTHR, 5)
step_kernel(const float* __restrict__ cur,
            const float* __restrict__ prev,
            const float* __restrict__ vp,
            const float* __restrict__ src,
            float* __restrict__ out,
            const float* __restrict__ ref) {
    __shared__ float sp[4][TILE_H][TILE_W];   // 4-deep ring

    const int tx = threadIdx.x;
    const int ty = threadIdx.y;
    const int x0 = blockIdx.x * SPANX;
    const int y0 = blockIdx.y * TY;
    const int z0 = blockIdx.z * ZC;
    const int gx = x0 + 4 * tx;
    const int gy = y0 + ty;
    const int tid = ty * TXT + tx;
    const int col = gy * NN + gx;

    int goff[3], sidx[3];
#pragma unroll
    for (int k = 0; k < 3; k++) {
        int i = tid + k * NTHR;
        if (i < NSLOT) {
            int sy = i / FW4;
            int sxx = i - sy * FW4;
            int yy = y0 - R + sy;
            int xx = x0 - R + 4 * sxx;
            sidx[k] = sy * TILE_W + 4 * sxx;
            goff[k] = (xx >= 0 && xx + 3 < NN && yy >= 0 && yy < NN)
                          ? (yy * NN + xx) : -1;
        } else {
            sidx[k] = -1;
            goff[k] = -1;
        }
    }

    uint32_t sb[4];
#pragma unroll
    for (int b = 0; b < 4; b++)
        sb[b] = (uint32_t)__cvta_generic_to_shared(&sp[b][0][0]);

    // Prologue: async fills for planes z0 (buf0), z0+1 (buf1)
    fill_plane_async(sb[0], cur + z0 * PLANE, goff, sidx);
    fill_plane_async(sb[1], cur + (z0 + 1) * PLANE, goff, sidx);

    // z-queue: planes z0-4 .. z0+4
    float4 q[9];
#pragma unroll
    for (int k = 0; k < 9; k++) {
        int gz = z0 - R + k;
        q[k] = (gz >= 0 && gz < NN) ? ldg4(&cur[gz * PLANE + col])
                                    : make_float4(0.f, 0.f, 0.f, 0.f);
    }

    const bool hasprev = (prev != nullptr);

    // Pointwise operands for the FIRST body (plane z0)
    const int idx0 = z0 * PLANE + col;
    float4 pv = hasprev ? ldg4(&prev[idx0]) : make_float4(0.f, 0.f, 0.f, 0.f);
    float4 vv = ldg4(&vp[idx0]);
    float4 sv = ldcs4(&src[idx0]);

    StepCtx<FINAL> c{cur, prev, vp, src, out, ref};
    const int sx = R + 4 * tx;
    const int syc = ty + R;

    double acc_s = 0.0;
    float acc_m = 0.0f;

#pragma unroll 1
    for (int iz = 0; iz < ZC; iz += 4) {
        plane_body<FINAL>(c, sp[0], sb[2], z0 + iz + 0, hasprev,
                          goff, sidx, col, q, pv, vv, sv, sx, syc, acc_s, acc_m);
        plane_body<FINAL>(c, sp[1], sb[3], z0 + iz + 1, hasprev,
                          goff, sidx, col, q, pv, vv, sv, sx, syc, acc_s, acc_m);
        plane_body<FINAL>(c, sp[2], sb[0], z0 + iz + 2, hasprev,
                          goff, sidx, col, q, pv, vv, sv, sx, syc, acc_s, acc_m);
        plane_body<FINAL>(c, sp[3], sb[1], z0 + iz + 3, hasprev,
                          goff, sidx, col, q, pv, vv, sv, sx, syc, acc_s, acc_m);
    }

    if (FINAL) {
#pragma unroll
        for (int o = 16; o > 0; o >>= 1) {
            acc_s += __shfl_down_sync(0xFFFFFFFFu, acc_s, o);
            acc_m = fmaxf(acc_m, __shfl_down_sync(0xFFFFFFFFu, acc_m, o));
        }
        __shared__ double ss[4];
        __shared__ float sm[4];
        int lane = tid & 31;
        int w = tid >> 5;
        if (lane == 0) { ss[w] = acc_s; sm[w] = acc_m; }
        __syncthreads();
        if (w == 0) {
            acc_s = (lane < 4) ? ss[lane] : 0.0;
            acc_m = (lane < 4) ? sm[lane] : 0.0f;
#pragma unroll
            for (int o = 2; o > 0; o >>= 1) {
                acc_s += __shfl_down_sync(0xFFFFFFFFu, acc_s, o);
                acc_m = fmaxf(acc_m, __shfl_down_sync(0xFFFFFFFFu, acc_m, o));
            }
            if (lane == 0) {
                atomicAdd(&g_sum, acc_s);
                atomicMax(&g_maxbits, __float_as_uint(acc_m));
            }
        }
    }
}

__global__ void finalize_kernel(float* d_out, int n) {
    d_out[0] = (float)(g_sum / (double)n);
    d_out[n + 1] = __uint_as_float(g_maxbits);
}

extern "C" void kernel_launch(void* const* d_in, const int* in_sizes, int n_in,
                              void* d_out, int out_size) {
    const float* vp  = (const float*)d_in[0];
    const float* src = (const float*)d_in[1];
    const float* ref = (const float*)d_in[2];

    static float* bufA = nullptr;
    static float* bufB = nullptr;
    if (!bufA) {
        cudaGetSymbolAddress((void**)&bufA, g_bufA);
        cudaGetSymbolAddress((void**)&bufB, g_bufB);
    }

    const bool has_scalars = (out_size >= VOL + 2);
    float* outp = has_scalars ? ((float*)d_out + 1) : (float*)d_out;

    dim3 blk(TXT, TY);
    dim3 grid(NN / SPANX, NN / TY, NN / ZC);   // (3, 24, 12) = 864 blocks

    init_accum_kernel<<<1, 1>>>();

    const float* s0 = src;

    step_kernel<false><<<grid, blk>>>(s0,   nullptr, vp, src + (size_t)1 * VOL, bufA, nullptr);
    step_kernel<false><<<grid, blk>>>(bufA, s0,      vp, src + (size_t)2 * VOL, bufB, nullptr);
    step_kernel<false><<<grid, blk>>>(bufB, bufA,    vp, src + (size_t)3 * VOL, bufA, nullptr);
    step_kernel<false><<<grid, blk>>>(bufA, bufB,    vp, src + (size_t)4 * VOL, bufB, nullptr);
    step_kernel<false><<<grid, blk>>>(bufB, bufA,    vp, src + (size_t)5 * VOL, bufA, nullptr);
    step_kernel<false><<<grid, blk>>>(bufA, bufB,    vp, src + (size_t)6 * VOL, bufB, nullptr);
    step_kernel<false><<<grid, blk>>>(bufB, bufA,    vp, src + (size_t)7 * VOL, bufA, nullptr);
    step_kernel<false><<<grid, blk>>>(bufA, bufB,    vp, src + (size_t)8 * VOL, bufB, nullptr);
    step_kernel<true><<<grid, blk>>>(bufB, bufA,     vp, src + (size_t)9 * VOL, outp, ref);

    if (has_scalars) {
        finalize_kernel<<<1, 1>>>((float*)d_out, VOL);
    }
}

// round 9
// speedup vs baseline: 1.1755x; 1.1755x over previous
#include <cuda_runtime.h>
#include <cuda_bf16.h>
#include <math.h>
#include <stdint.h>

// ---------------------------------------------------------------------------
// 25-pt (radius-4, 3-axis) wave stencil, 10 scan steps (first trivial),
// then loss = mean((out-ref)^2), max_abs = max|out-ref|.
// R9: R7 pipeline (cp.async ring distance 2, q-head prefetch 1 body ahead,
// pv/vv/sv same-body) + FULLY UNROLLED 16 z-bodies with register-rotated
// z-queue (9 named float4 refs, period-9 rotation) -> zero queue-shift MOVs.
// ---------------------------------------------------------------------------

#define NN 192
#define PLANE (NN * NN)
#define VOL (NN * NN * NN)

#define TXT 16
#define TY 8
#define NTHR (TXT * TY)          // 128
#define SPANX (TXT * 4)          // 64 x-points per block
#define ZC 16
#define R  4

#define TILE_H (TY + 2 * R)      // 16
#define TILE_WU (SPANX + 2 * R)  // 72 floats used
#define TILE_W 80                // padded row stride
#define FW4 (TILE_WU / 4)        // 18 float4 per row
#define NSLOT (TILE_H * FW4)     // 288 fill slots

#define C0 ((float)(-205.0 / 72.0 / 400.0))
#define C1 ((float)(8.0 / 5.0 / 400.0))
#define C2 ((float)(-1.0 / 5.0 / 400.0))
#define C3 ((float)(8.0 / 315.0 / 400.0))
#define C4 ((float)(-1.0 / 560.0 / 400.0))

__device__ float g_bufA[VOL];
__device__ float g_bufB[VOL];
__device__ double g_sum;
__device__ unsigned int g_maxbits;

__global__ void init_accum_kernel() {
    g_sum = 0.0;
    g_maxbits = 0u;
}

__device__ __forceinline__ float4 ldg4(const float* p) {
    return *reinterpret_cast<const float4*>(p);
}
__device__ __forceinline__ float4 ldcs4(const float* p) {
    float4 v;
    asm volatile("ld.global.cs.v4.f32 {%0,%1,%2,%3}, [%4];"
                 : "=f"(v.x), "=f"(v.y), "=f"(v.z), "=f"(v.w) : "l"(p));
    return v;
}
__device__ __forceinline__ float ldcs1(const float* p) {
    float v;
    asm volatile("ld.global.cs.f32 %0, [%1];" : "=f"(v) : "l"(p));
    return v;
}

__device__ __forceinline__ void fill_plane_async(
    uint32_t sbase, const float* gplane, const int* goff, const int* sidx) {
#pragma unroll
    for (int k = 0; k < 3; k++) {
        if (sidx[k] >= 0) {
            const float* srcp = (goff[k] >= 0) ? (gplane + goff[k]) : gplane;
            int sz = (goff[k] >= 0) ? 16 : 0;
            asm volatile("cp.async.cg.shared.global [%0], [%1], 16, %2;"
                         :: "r"(sbase + (uint32_t)sidx[k] * 4u), "l"(srcp), "r"(sz));
        }
    }
    asm volatile("cp.async.commit_group;" ::: "memory");
}

// Body for plane z. Consumes tile(z) + qm4..qp4 (planes z-4..z+4) and
// same-body pv/vv/sv. Issues: tile fill for z+2; LDG of plane z+5 written
// into OUTGOING register qm4 (the next call's qp4, via rotation).
template <bool FINAL>
__device__ __forceinline__ void plane_body(
    const float* __restrict__ cur, const float* __restrict__ prev,
    const float* __restrict__ vp, const float* __restrict__ src,
    float* __restrict__ out, const float* __restrict__ ref,
    const float (&consume)[TILE_H][TILE_W],
    uint32_t fillbase,
    int z, bool hasprev,
    const int* goff, const int* sidx, int col,
    float4& qm4, float4& qm3, float4& qm2, float4& qm1, float4& qc,
    float4& qp1, float4& qp2, float4& qp3, float4& qp4,
    int sx, int syc,
    double& acc_s, float& acc_m) {

    const int idx = z * PLANE + col;

    // ---- issue async tile fill for plane z+2 (clamped) ----
    {
        int zf = z + 2;
        if (zf > NN - 1) zf = NN - 1;
        fill_plane_async(fillbase, cur + zf * PLANE, goff, sidx);
    }

    // ---- prefetch next q-head (plane z+5, consumed NEXT body) ----
    float4 qn;
    {
        int zp = z + 5;
        qn = (zp < NN) ? ldg4(&cur[zp * PLANE + col])
                       : make_float4(0.f, 0.f, 0.f, 0.f);
    }
    // pointwise operands (same-body; R8 showed prefetching these loses)
    const float4 pv = hasprev ? ldg4(&prev[idx]) : make_float4(0.f, 0.f, 0.f, 0.f);
    const float4 vv = ldg4(&vp[idx]);
    const float4 sv = ldcs4(&src[idx]);

    // ---- wait for tile(z), then compute ----
    asm volatile("cp.async.wait_group 2;" ::: "memory");
    __syncthreads();

    float xs[12];
#pragma unroll
    for (int j = 0; j < 3; j++) {
        float4 t = *reinterpret_cast<const float4*>(&consume[syc][sx - 4 + 4 * j]);
        xs[4 * j + 0] = t.x;
        xs[4 * j + 1] = t.y;
        xs[4 * j + 2] = t.z;
        xs[4 * j + 3] = t.w;
    }

    float lap[4];
    {
        const float* q4 = &qc.x;
#pragma unroll
        for (int p = 0; p < 4; p++) lap[p] = (3.0f * C0) * q4[p];
    }
    {
        float4 ym = *reinterpret_cast<const float4*>(&consume[syc - 1][sx]);
        float4 yp = *reinterpret_cast<const float4*>(&consume[syc + 1][sx]);
        const float* a = &ym.x;
        const float* b = &yp.x;
        const float* m = &qm1.x;
        const float* pl = &qp1.x;
#pragma unroll
        for (int p = 0; p < 4; p++)
            lap[p] += C1 * (m[p] + pl[p] + a[p] + b[p] + xs[p + 3] + xs[p + 5]);
    }
    {
        float4 ym = *reinterpret_cast<const float4*>(&consume[syc - 2][sx]);
        float4 yp = *reinterpret_cast<const float4*>(&consume[syc + 2][sx]);
        const float* a = &ym.x;
        const float* b = &yp.x;
        const float* m = &qm2.x;
        const float* pl = &qp2.x;
#pragma unroll
        for (int p = 0; p < 4; p++)
            lap[p] += C2 * (m[p] + pl[p] + a[p] + b[p] + xs[p + 2] + xs[p + 6]);
    }
    {
        float4 ym = *reinterpret_cast<const float4*>(&consume[syc - 3][sx]);
        float4 yp = *reinterpret_cast<const float4*>(&consume[syc + 3][sx]);
        const float* a = &ym.x;
        const float* b = &yp.x;
        const float* m = &qm3.x;
        const float* pl = &qp3.x;
#pragma unroll
        for (int p = 0; p < 4; p++)
            lap[p] += C3 * (m[p] + pl[p] + a[p] + b[p] + xs[p + 1] + xs[p + 7]);
    }
    {
        float4 ym = *reinterpret_cast<const float4*>(&consume[syc - 4][sx]);
        float4 yp = *reinterpret_cast<const float4*>(&consume[syc + 4][sx]);
        const float* a = &ym.x;
        const float* b = &yp.x;
        const float* m = &qm4.x;
        const float* pl = &qp4.x;
#pragma unroll
        for (int p = 0; p < 4; p++)
            lap[p] += C4 * (m[p] + pl[p] + a[p] + b[p] + xs[p] + xs[p + 8]);
    }

    float4 upd;
    {
        const float* q4 = &qc.x;
        const float* pvp = &pv.x;
        const float* vvp = &vv.x;
        const float* svp = &sv.x;
        float* u = &upd.x;
#pragma unroll
        for (int p = 0; p < 4; p++)
            u[p] = 2.0f * q4[p] - pvp[p] + vvp[p] * lap[p] + svp[p];
    }

    if (FINAL) {
        const float* u = &upd.x;
#pragma unroll
        for (int p = 0; p < 4; p++) {
            out[idx + p] = u[p];
            float e = u[p] - ldcs1(&ref[idx + p]);
            acc_s += (double)e * (double)e;
            acc_m = fmaxf(acc_m, fabsf(e));
        }
    } else {
        *reinterpret_cast<float4*>(&out[idx]) = upd;
    }

    // rotate: outgoing register takes the prefetched head (becomes qp4 next call)
    qm4 = qn;
}

template <bool FINAL>
__global__ void __launch_bounds__(NTHR, 6)
step_kernel(const float* __restrict__ cur,
            const float* __restrict__ prev,
            const float* __restrict__ vp,
            const float* __restrict__ src,
            float* __restrict__ out,
            const float* __restrict__ ref) {
    __shared__ float sp[4][TILE_H][TILE_W];   // 4-deep ring

    const int tx = threadIdx.x;
    const int ty = threadIdx.y;
    const int x0 = blockIdx.x * SPANX;
    const int y0 = blockIdx.y * TY;
    const int z0 = blockIdx.z * ZC;
    const int gx = x0 + 4 * tx;
    const int gy = y0 + ty;
    const int tid = ty * TXT + tx;
    const int col = gy * NN + gx;

    int goff[3], sidx[3];
#pragma unroll
    for (int k = 0; k < 3; k++) {
        int i = tid + k * NTHR;
        if (i < NSLOT) {
            int sy = i / FW4;
            int sxx = i - sy * FW4;
            int yy = y0 - R + sy;
            int xx = x0 - R + 4 * sxx;
            sidx[k] = sy * TILE_W + 4 * sxx;
            goff[k] = (xx >= 0 && xx + 3 < NN && yy >= 0 && yy < NN)
                          ? (yy * NN + xx) : -1;
        } else {
            sidx[k] = -1;
            goff[k] = -1;
        }
    }

    uint32_t sb[4];
#pragma unroll
    for (int b = 0; b < 4; b++)
        sb[b] = (uint32_t)__cvta_generic_to_shared(&sp[b][0][0]);

    // Prologue: async fills for planes z0 (buf0), z0+1 (buf1)
    fill_plane_async(sb[0], cur + z0 * PLANE, goff, sidx);
    fill_plane_async(sb[1], cur + (z0 + 1) * PLANE, goff, sidx);

    // z-queue: 9 NAMED registers, planes z0-4 .. z0+4
    float4 r0, r1, r2, r3, r4, r5, r6, r7, r8;
    {
        float4* rr[9] = {&r0, &r1, &r2, &r3, &r4, &r5, &r6, &r7, &r8};
#pragma unroll
        for (int k = 0; k < 9; k++) {
            int gz = z0 - R + k;
            *rr[k] = (gz >= 0 && gz < NN) ? ldg4(&cur[gz * PLANE + col])
                                          : make_float4(0.f, 0.f, 0.f, 0.f);
        }
    }

    const bool hasprev = (prev != nullptr);
    const int sx = R + 4 * tx;
    const int syc = ty + R;

    double acc_s = 0.0;
    float acc_m = 0.0f;

    // 16 fully-unrolled bodies; queue rotated by argument order (period 9).
#define PB(I, A, B, C, D, E, F, G, H, J)                                      \
    plane_body<FINAL>(cur, prev, vp, src, out, ref, sp[(I) & 3],              \
                      sb[((I) + 2) & 3], z0 + (I), hasprev, goff, sidx, col,  \
                      r##A, r##B, r##C, r##D, r##E, r##F, r##G, r##H, r##J,   \
                      sx, syc, acc_s, acc_m)

    PB(0, 0, 1, 2, 3, 4, 5, 6, 7, 8);
    PB(1, 1, 2, 3, 4, 5, 6, 7, 8, 0);
    PB(2, 2, 3, 4, 5, 6, 7, 8, 0, 1);
    PB(3, 3, 4, 5, 6, 7, 8, 0, 1, 2);
    PB(4, 4, 5, 6, 7, 8, 0, 1, 2, 3);
    PB(5, 5, 6, 7, 8, 0, 1, 2, 3, 4);
    PB(6, 6, 7, 8, 0, 1, 2, 3, 4, 5);
    PB(7, 7, 8, 0, 1, 2, 3, 4, 5, 6);
    PB(8, 8, 0, 1, 2, 3, 4, 5, 6, 7);
    PB(9, 0, 1, 2, 3, 4, 5, 6, 7, 8);
    PB(10, 1, 2, 3, 4, 5, 6, 7, 8, 0);
    PB(11, 2, 3, 4, 5, 6, 7, 8, 0, 1);
    PB(12, 3, 4, 5, 6, 7, 8, 0, 1, 2);
    PB(13, 4, 5, 6, 7, 8, 0, 1, 2, 3);
    PB(14, 5, 6, 7, 8, 0, 1, 2, 3, 4);
    PB(15, 6, 7, 8, 0, 1, 2, 3, 4, 5);
#undef PB

    if (FINAL) {
#pragma unroll
        for (int o = 16; o > 0; o >>= 1) {
            acc_s += __shfl_down_sync(0xFFFFFFFFu, acc_s, o);
            acc_m = fmaxf(acc_m, __shfl_down_sync(0xFFFFFFFFu, acc_m, o));
        }
        __shared__ double ss[4];
        __shared__ float sm[4];
        int lane = tid & 31;
        int w = tid >> 5;
        if (lane == 0) { ss[w] = acc_s; sm[w] = acc_m; }
        __syncthreads();
        if (w == 0) {
            acc_s = (lane < 4) ? ss[lane] : 0.0;
            acc_m = (lane < 4) ? sm[lane] : 0.0f;
#pragma unroll
            for (int o = 2; o > 0; o >>= 1) {
                acc_s += __shfl_down_sync(0xFFFFFFFFu, acc_s, o);
                acc_m = fmaxf(acc_m, __shfl_down_sync(0xFFFFFFFFu, acc_m, o));
            }
            if (lane == 0) {
                atomicAdd(&g_sum, acc_s);
                atomicMax(&g_maxbits, __float_as_uint(acc_m));
            }
        }
    }
}

__global__ void finalize_kernel(float* d_out, int n) {
    d_out[0] = (float)(g_sum / (double)n);
    d_out[n + 1] = __uint_as_float(g_maxbits);
}

extern "C" void kernel_launch(void* const* d_in, const int* in_sizes, int n_in,
                              void* d_out, int out_size) {
    const float* vp  = (const float*)d_in[0];
    const float* src = (const float*)d_in[1];
    const float* ref = (const float*)d_in[2];

    static float* bufA = nullptr;
    static float* bufB = nullptr;
    if (!bufA) {
        cudaGetSymbolAddress((void**)&bufA, g_bufA);
        cudaGetSymbolAddress((void**)&bufB, g_bufB);
    }

    const bool has_scalars = (out_size >= VOL + 2);
    float* outp = has_scalars ? ((float*)d_out + 1) : (float*)d_out;

    dim3 blk(TXT, TY);
    dim3 grid(NN / SPANX, NN / TY, NN / ZC);   // (3, 24, 12) = 864 blocks

    init_accum_kernel<<<1, 1>>>();

    const float* s0 = src;

    step_kernel<false><<<grid, blk>>>(s0,   nullptr, vp, src + (size_t)1 * VOL, bufA, nullptr);
    step_kernel<false><<<grid, blk>>>(bufA, s0,      vp, src + (size_t)2 * VOL, bufB, nullptr);
    step_kernel<false><<<grid, blk>>>(bufB, bufA,    vp, src + (size_t)3 * VOL, bufA, nullptr);
    step_kernel<false><<<grid, blk>>>(bufA, bufB,    vp, src + (size_t)4 * VOL, bufB, nullptr);
    step_kernel<false><<<grid, blk>>>(bufB, bufA,    vp, src + (size_t)5 * VOL, bufA, nullptr);
    step_kernel<false><<<grid, blk>>>(bufA, bufB,    vp, src + (size_t)6 * VOL, bufB, nullptr);
    step_kernel<false><<<grid, blk>>>(bufB, bufA,    vp, src + (size_t)7 * VOL, bufA, nullptr);
    step_kernel<false><<<grid, blk>>>(bufA, bufB,    vp, src + (size_t)8 * VOL, bufB, nullptr);
    step_kernel<true><<<grid, blk>>>(bufB, bufA,     vp, src + (size_t)9 * VOL, outp, ref);

    if (has_scalars) {
        finalize_kernel<<<1, 1>>>((float*)d_out, VOL);
    }
}